// round 6
// baseline (speedup 1.0000x reference)
#include <cuda_runtime.h>
#include <math.h>
#include <stdint.h>

#define BATCH 8
#define CH    256
#define NQ    2048
#define MPTS  4096
#define KNN   10

static __device__ float g_xT   [(size_t)BATCH * NQ * CH];   // (b,n,c)
static __device__ float g_Yqkt [(size_t)BATCH * NQ * CH];   // (b,n,c)
static __device__ float g_Yv   [(size_t)BATCH * CH * NQ];   // (b,c,n)
static __device__ float g_energy[(size_t)BATCH * NQ * NQ];  // (b,n,m)
static __device__ float g_rmax [BATCH * NQ];
static __device__ float g_rinv [BATCH * NQ];
static __device__ float g_colsum[BATCH * NQ];
static __device__ float g_dbufT[(size_t)BATCH * NQ * CH];   // (b,n,c)
static __device__ float g_feat [(size_t)BATCH * CH * NQ];   // (b,c,n)
static __device__ float g_query[(size_t)BATCH * 3 * NQ];

__device__ __forceinline__ uint32_t smem_u32(const void* p) {
    uint32_t a;
    asm("{ .reg .u64 t; cvta.to.shared.u64 t, %1; cvt.u32.u64 %0, t; }" : "=r"(a) : "l"(p));
    return a;
}
__device__ __forceinline__ uint32_t f2tf32(float f) {
    uint32_t r;
    asm("cvt.rna.tf32.f32 %0, %1;" : "=r"(r) : "f"(f));
    return r;
}
#define LDSM_X4(r0, r1, r2, r3, addr) \
    asm volatile("ldmatrix.sync.aligned.m8n8.x4.shared.b16 {%0,%1,%2,%3}, [%4];" \
        : "=r"(r0), "=r"(r1), "=r"(r2), "=r"(r3) : "r"(addr))
#define MMA4(d, a, bb) \
    asm volatile("mma.sync.aligned.m16n8k8.row.col.f32.tf32.tf32.f32 " \
        "{%0,%1,%2,%3}, {%4,%5,%6,%7}, {%8,%9}, {%0,%1,%2,%3};" \
        : "+f"((d)[0]), "+f"((d)[1]), "+f"((d)[2]), "+f"((d)[3]) \
        : "r"((a)[0]), "r"((a)[1]), "r"((a)[2]), "r"((a)[3]), \
          "r"((bb)[0]), "r"((bb)[1]))

// ===========================================================================
// mma.sync tf32 GEMM: D[128 x 128] = A(128 rows, K) @ B(128 rows, K)^T.
// PASSES 3: hi/lo 3xTF32 (~fp32); PASSES 1: plain tf32.
// AFILL 0: A K-major float4 fill. AFILL 1: A = softmax(energy)^T on the fly:
//          A[m][k=n] = tf32(exp(energy[n][m]-rmax[n])*rinv[n])  (PASSES==1)
// MODE 0: Out[row][col] = acc
// MODE 1: Out[row][col] = acc + bias[row]
// MODE 2: Out[row*ldc+col] = xres[b][col][row] - acc/(1e-9+colsum[b][row])
// MODE 3: Out[row][col] = xres[b][row][col] + relu(BN(acc+bias[row]))
// SMEM single stage: Ah(16K) Bh(16K) [Al(16K) Bl(16K)], SW128-style swizzle.
// ===========================================================================
template<int PASSES, int MODE, int AFILL>
__global__ __launch_bounds__(256)
void mma_gemm(const float* __restrict__ Aall, size_t sA, int lda,
              const float* __restrict__ Ball, size_t sB, int ldb,
              float* __restrict__ Out, size_t sC, int ldc, int KTOT,
              const float* __restrict__ bias, const float* __restrict__ gamma,
              const float* __restrict__ beta, const float* __restrict__ xres,
              const float* __restrict__ colsum,
              const float* __restrict__ rmax, const float* __restrict__ rinv)
{
    extern __shared__ char DSM[];
    const int b = blockIdx.z;
    const int a0 = blockIdx.x * 128;
    const int boff = blockIdx.y * 128;
    const float* Ab = Aall + (size_t)b * sA;
    const float* Arow = Ab + (size_t)a0 * lda;
    const float* Brow = Ball + (size_t)b * sB + (size_t)boff * ldb;
    const int tid = threadIdx.x, lane = tid & 31;
    const int wm = (tid >> 5) >> 2, wn = (tid >> 5) & 3;
    const uint32_t sbase = smem_u32(DSM);

    float acc[4][4][4];
#pragma unroll
    for (int i = 0; i < 4; i++)
#pragma unroll
        for (int j = 0; j < 4; j++)
#pragma unroll
            for (int k = 0; k < 4; k++) acc[i][j][k] = 0.f;

    float4 pa[4], pb[4];
#pragma unroll
    for (int i = 0; i < 4; i++) {
        int idx = tid + i * 256;
        if (AFILL == 0)
            pa[i] = *(const float4*)(Arow + (size_t)(idx >> 3) * lda + (idx & 7) * 4);
        else
            pa[i] = *(const float4*)(Ab + (size_t)(idx >> 5) * lda + a0 + (idx & 31) * 4);
        pb[i] = *(const float4*)(Brow + (size_t)(idx >> 3) * ldb + (idx & 7) * 4);
    }

    const int NIT = KTOT / 32;
    for (int it = 0; it < NIT; it++) {
        const int k0c = it * 32;
#pragma unroll
        for (int i = 0; i < 4; i++) {
            int idx = tid + i * 256;
            if (AFILL == 0) {
                int m = idx >> 3, j = idx & 7;
                uint32_t off = (uint32_t)(m * 128 + ((j * 16) ^ ((m & 7) * 16)));
                float4 v = pa[i];
                uint4 h;
                h.x = f2tf32(v.x); h.y = f2tf32(v.y); h.z = f2tf32(v.z); h.w = f2tf32(v.w);
                *(uint4*)(DSM + off) = h;
                if (PASSES == 3) {
                    float4 l = make_float4(v.x - __uint_as_float(h.x), v.y - __uint_as_float(h.y),
                                           v.z - __uint_as_float(h.z), v.w - __uint_as_float(h.w));
                    *(float4*)(DSM + 32768 + off) = l;
                }
            } else {
                int nl = idx >> 5, mg0 = (idx & 31) * 4;
                float s = rmax[b * NQ + k0c + nl];
                float rv = rinv[b * NQ + k0c + nl];
                float vv[4] = {pa[i].x, pa[i].y, pa[i].z, pa[i].w};
#pragma unroll
                for (int j = 0; j < 4; j++) {
                    int r = mg0 + j;
                    uint32_t off = (uint32_t)(r * 128 + ((nl * 4) ^ ((r & 7) * 16)));
                    *(uint32_t*)(DSM + off) = f2tf32(__expf(vv[j] - s) * rv);
                }
            }
            {
                int m = idx >> 3, j = idx & 7;
                uint32_t off = (uint32_t)(m * 128 + ((j * 16) ^ ((m & 7) * 16)));
                float4 v = pb[i];
                uint4 h;
                h.x = f2tf32(v.x); h.y = f2tf32(v.y); h.z = f2tf32(v.z); h.w = f2tf32(v.w);
                *(uint4*)(DSM + 16384 + off) = h;
                if (PASSES == 3) {
                    float4 l = make_float4(v.x - __uint_as_float(h.x), v.y - __uint_as_float(h.y),
                                           v.z - __uint_as_float(h.z), v.w - __uint_as_float(h.w));
                    *(float4*)(DSM + 49152 + off) = l;
                }
            }
        }
        __syncthreads();
        if (it + 1 < NIT) {
            int k0 = (it + 1) * 32;
#pragma unroll
            for (int i = 0; i < 4; i++) {
                int idx = tid + i * 256;
                if (AFILL == 0)
                    pa[i] = *(const float4*)(Arow + (size_t)(idx >> 3) * lda + k0 + (idx & 7) * 4);
                else
                    pa[i] = *(const float4*)(Ab + (size_t)(k0 + (idx >> 5)) * lda + a0 + (idx & 31) * 4);
                pb[i] = *(const float4*)(Brow + (size_t)(idx >> 3) * ldb + k0 + (idx & 7) * 4);
            }
        }
        const uint32_t Ah = sbase, Bh = sbase + 16384;
        const uint32_t Al = sbase + 32768, Bl = sbase + 49152;
#pragma unroll
        for (int ks = 0; ks < 4; ks++) {
            uint32_t ahf[4][4], bhf[4][2], alf[4][4], blf[4][2];
            const uint32_t ca = (uint32_t)(ks * 32 + (lane & 16));
            const int ra = wm * 64 + (lane & 15);
#pragma unroll
            for (int mt = 0; mt < 4; mt++) {
                int r = ra + mt * 16;
                uint32_t o = (uint32_t)(r * 128) + (ca ^ (uint32_t)((r & 7) * 16));
                LDSM_X4(ahf[mt][0], ahf[mt][1], ahf[mt][2], ahf[mt][3], Ah + o);
                if (PASSES == 3)
                    LDSM_X4(alf[mt][0], alf[mt][1], alf[mt][2], alf[mt][3], Al + o);
            }
            const uint32_t cb = (uint32_t)(ks * 32 + ((lane & 8) << 1));
            const int rbb = wn * 32 + (lane & 7) + ((lane & 16) >> 1);
#pragma unroll
            for (int np = 0; np < 2; np++) {
                int r = rbb + np * 16;
                uint32_t o = (uint32_t)(r * 128) + (cb ^ (uint32_t)((r & 7) * 16));
                LDSM_X4(bhf[2 * np][0], bhf[2 * np][1], bhf[2 * np + 1][0], bhf[2 * np + 1][1], Bh + o);
                if (PASSES == 3)
                    LDSM_X4(blf[2 * np][0], blf[2 * np][1], blf[2 * np + 1][0], blf[2 * np + 1][1], Bl + o);
            }
#pragma unroll
            for (int mt = 0; mt < 4; mt++)
#pragma unroll
                for (int nt = 0; nt < 4; nt++) {
                    MMA4(acc[mt][nt], ahf[mt], bhf[nt]);
                    if (PASSES == 3) {
                        MMA4(acc[mt][nt], ahf[mt], blf[nt]);
                        MMA4(acc[mt][nt], alf[mt], bhf[nt]);
                    }
                }
        }
        __syncthreads();
    }

    const int gid = lane >> 2, tig = lane & 3;
    float* Ob = Out + (size_t)b * sC;
    const float bns = 0.9999950000374996f;  // 1/sqrt(1+1e-5)
#pragma unroll
    for (int mt = 0; mt < 4; mt++) {
        int r0 = a0 + wm * 64 + mt * 16 + gid;
        int r1 = r0 + 8;
        if (MODE == 0 || MODE == 1) {
            float b0 = 0.f, b1 = 0.f;
            if (MODE == 1) { b0 = bias[r0]; b1 = bias[r1]; }
#pragma unroll
            for (int nt = 0; nt < 4; nt++) {
                int c = boff + wn * 32 + nt * 8 + 2 * tig;
                *(float2*)(Ob + (size_t)r0 * ldc + c) =
                    make_float2(acc[mt][nt][0] + b0, acc[mt][nt][1] + b0);
                *(float2*)(Ob + (size_t)r1 * ldc + c) =
                    make_float2(acc[mt][nt][2] + b1, acc[mt][nt][3] + b1);
            }
        } else if (MODE == 2) {
            const float* xb = xres + (size_t)b * CH * NQ;
            float inv0 = 1.f / (1e-9f + colsum[b * NQ + r0]);
            float inv1 = 1.f / (1e-9f + colsum[b * NQ + r1]);
            float* o0 = Ob + (size_t)r0 * ldc;
            float* o1 = Ob + (size_t)r1 * ldc;
#pragma unroll
            for (int nt = 0; nt < 4; nt++) {
                int c = boff + wn * 32 + nt * 8 + 2 * tig;
                o0[c]     = xb[(size_t)c * NQ + r0]       - acc[mt][nt][0] * inv0;
                o0[c + 1] = xb[(size_t)(c + 1) * NQ + r0] - acc[mt][nt][1] * inv0;
                o1[c]     = xb[(size_t)c * NQ + r1]       - acc[mt][nt][2] * inv1;
                o1[c + 1] = xb[(size_t)(c + 1) * NQ + r1] - acc[mt][nt][3] * inv1;
            }
        } else {   // MODE 3
            float bb0 = bias[r0], g0 = gamma[r0], be0 = beta[r0];
            float bb1 = bias[r1], g1 = gamma[r1], be1 = beta[r1];
            const float* xb = xres + (size_t)b * CH * NQ;
#pragma unroll
            for (int nt = 0; nt < 4; nt++) {
                int c = boff + wn * 32 + nt * 8 + 2 * tig;
                float2 x0 = *(const float2*)(xb + (size_t)r0 * NQ + c);
                float2 x1 = *(const float2*)(xb + (size_t)r1 * NQ + c);
                float v0 = (acc[mt][nt][0] + bb0) * bns * g0 + be0;
                float v1 = (acc[mt][nt][1] + bb0) * bns * g0 + be0;
                float v2 = (acc[mt][nt][2] + bb1) * bns * g1 + be1;
                float v3 = (acc[mt][nt][3] + bb1) * bns * g1 + be1;
                *(float2*)(Ob + (size_t)r0 * ldc + c) =
                    make_float2(x0.x + fmaxf(v0, 0.f), x0.y + fmaxf(v1, 0.f));
                *(float2*)(Ob + (size_t)r1 * ldc + c) =
                    make_float2(x1.x + fmaxf(v2, 0.f), x1.y + fmaxf(v3, 0.f));
            }
        }
    }
}

// xT[b][n][c] = x[b][c][n]
__global__ __launch_bounds__(256)
void transpose_x(const float* __restrict__ x, float* __restrict__ xT)
{
    __shared__ float tl[32][33];
    const int b = blockIdx.z;
    const int n0 = blockIdx.x * 32, c0 = blockIdx.y * 32;
    const int tx = threadIdx.x & 31, ty = threadIdx.x >> 5;
#pragma unroll
    for (int i = 0; i < 4; i++)
        tl[ty + i * 8][tx] = x[(size_t)b * CH * NQ + (size_t)(c0 + ty + i * 8) * NQ + n0 + tx];
    __syncthreads();
#pragma unroll
    for (int i = 0; i < 4; i++)
        xT[(size_t)b * NQ * CH + (size_t)(n0 + ty + i * 8) * CH + c0 + tx] = tl[tx][ty + i * 8];
}

// row max + 1/sum(exp) per energy row
__global__ __launch_bounds__(256)
void rowstat(const float* __restrict__ e, float* __restrict__ rmax, float* __restrict__ rinv)
{
    const float* row = e + (size_t)blockIdx.x * NQ;
    const int t = threadIdx.x;
    float v[8], mx = -1e30f;
#pragma unroll
    for (int i = 0; i < 8; i++) { v[i] = row[t + i * 256]; mx = fmaxf(mx, v[i]); }
    __shared__ float red[8], red2[8];
#pragma unroll
    for (int off = 16; off; off >>= 1) mx = fmaxf(mx, __shfl_xor_sync(~0u, mx, off));
    if ((t & 31) == 0) red[t >> 5] = mx;
    __syncthreads();
    mx = red[0];
#pragma unroll
    for (int i = 1; i < 8; i++) mx = fmaxf(mx, red[i]);
    float s = 0.f;
#pragma unroll
    for (int i = 0; i < 8; i++) s += __expf(v[i] - mx);
#pragma unroll
    for (int off = 16; off; off >>= 1) s += __shfl_xor_sync(~0u, s, off);
    if ((t & 31) == 0) red2[t >> 5] = s;
    __syncthreads();
    if (t == 0) {
        s = red2[0];
#pragma unroll
        for (int i = 1; i < 8; i++) s += red2[i];
        rmax[blockIdx.x] = mx;
        rinv[blockIdx.x] = 1.f / s;
    }
}

__global__ void zero_kernel(float* __restrict__ p, int n)
{
    int i = blockIdx.x * blockDim.x + threadIdx.x;
    if (i < n) p[i] = 0.f;
}

// colsum[b][m] += sum_n exp(e[b][n][m]-rmax)*rinv
__global__ __launch_bounds__(256)
void colsum_e(const float* __restrict__ e, const float* __restrict__ rmax,
              const float* __restrict__ rinv, float* __restrict__ cs)
{
    const int b = blockIdx.z;
    const int m = blockIdx.x * 256 + threadIdx.x;
    const int n0 = blockIdx.y * 256;
    const float* p = e + ((size_t)(b * NQ + n0)) * NQ + m;
    float s = 0.f;
#pragma unroll 4
    for (int n = 0; n < 256; n++) {
        int r = b * NQ + n0 + n;
        s += __expf(p[(size_t)n * NQ] - rmax[r]) * rinv[r];
    }
    atomicAdd(&cs[b * NQ + m], s);
}

// query[b][j][n] = sum_c Wp[j][c]*feat[b][c][n] + bp[j]
__global__ __launch_bounds__(256)
void query_kernel(const float* __restrict__ feat, const float* __restrict__ Wp,
                  const float* __restrict__ bp, float* __restrict__ q)
{
    const int n = blockIdx.x * 256 + threadIdx.x;
    const int b = blockIdx.y;
    const float* f = feat + (size_t)b * CH * NQ + n;
    float a0 = 0.f, a1 = 0.f, a2 = 0.f;
#pragma unroll 4
    for (int c = 0; c < CH; c++) {
        float fv = f[(size_t)c * NQ];
        a0 = fmaf(Wp[c], fv, a0);
        a1 = fmaf(Wp[CH + c], fv, a1);
        a2 = fmaf(Wp[2 * CH + c], fv, a2);
    }
    size_t o = (size_t)b * 3 * NQ + n;
    q[o] = a0 + bp[0]; q[o + NQ] = a1 + bp[1]; q[o + 2 * NQ] = a2 + bp[2];
}

// soft projection: warp-per-query top-10 + softmax weighted sum
__global__ __launch_bounds__(256)
void softproj_kernel(const float* __restrict__ pc, const float* __restrict__ query,
                     const float* __restrict__ temp, float* __restrict__ out)
{
    __shared__ float spx[MPTS], spy[MPTS], spz[MPTS];
    const int b = blockIdx.x;
    const float* p = pc + (size_t)b * 3 * MPTS;
    for (int i = threadIdx.x; i < MPTS; i += 256) {
        spx[i] = p[i]; spy[i] = p[MPTS + i]; spz[i] = p[2 * MPTS + i];
    }
    __syncthreads();

    const float t = temp[0];
    const float invsig = 1.f / (fmaxf(t * t, 1e-4f) + 1e-8f);
    const int warp = threadIdx.x >> 5, lane = threadIdx.x & 31;
    const int qbase = blockIdx.y * 64;

    for (int qq = 0; qq < 8; ++qq) {
        const int n = qbase + warp * 8 + qq;
        const float qx = query[((size_t)b * 3) * NQ + n];
        const float qy = query[((size_t)b * 3 + 1) * NQ + n];
        const float qz = query[((size_t)b * 3 + 2) * NQ + n];

        float d[KNN]; int idx[KNN];
#pragma unroll
        for (int i = 0; i < KNN; i++) { d[i] = 1e30f; idx[i] = 0; }
        for (int m = lane; m < MPTS; m += 32) {
            float dx = spx[m] - qx, dy = spy[m] - qy, dz = spz[m] - qz;
            float dd = fmaf(dx, dx, fmaf(dy, dy, dz * dz));
            if (dd < d[KNN - 1]) {
                d[KNN - 1] = dd; idx[KNN - 1] = m;
#pragma unroll
                for (int j = KNN - 1; j > 0; --j)
                    if (d[j] < d[j - 1]) {
                        float td = d[j]; d[j] = d[j - 1]; d[j - 1] = td;
                        int ti = idx[j]; idx[j] = idx[j - 1]; idx[j - 1] = ti;
                    }
            }
        }
        float wsum = 0.f, ox = 0.f, oy = 0.f, oz = 0.f, dmin = 0.f;
#pragma unroll
        for (int k = 0; k < KNN; k++) {
            float cd = d[0]; int ci = idx[0];
#pragma unroll
            for (int off = 16; off; off >>= 1) {
                float od = __shfl_xor_sync(~0u, cd, off);
                int   oi = __shfl_xor_sync(~0u, ci, off);
                if (od < cd || (od == cd && oi < ci)) { cd = od; ci = oi; }
            }
            if (k == 0) dmin = cd;
            float w = __expf(-(cd - dmin) * invsig);
            wsum += w;
            ox = fmaf(w, spx[ci], ox); oy = fmaf(w, spy[ci], oy); oz = fmaf(w, spz[ci], oz);
            bool iwin = (d[0] == cd && idx[0] == ci);
            unsigned bal = __ballot_sync(~0u, iwin);
            if (lane == (__ffs(bal) - 1)) {
#pragma unroll
                for (int j = 0; j < KNN - 1; j++) { d[j] = d[j + 1]; idx[j] = idx[j + 1]; }
                d[KNN - 1] = 1e30f; idx[KNN - 1] = 0;
            }
        }
        if (lane == 0) {
            float inv = 1.f / wsum;
            out[((size_t)b * 3) * NQ + n] = ox * inv;
            out[((size_t)b * 3 + 1) * NQ + n] = oy * inv;
            out[((size_t)b * 3 + 2) * NQ + n] = oz * inv;
        }
    }
}

// ---------------------------------------------------------------------------
extern "C" void kernel_launch(void* const* d_in, const int* in_sizes, int n_in,
                              void* d_out, int out_size)
{
    const float* x     = (const float*)d_in[0];
    const float* pc    = (const float*)d_in[1];
    const float* Wqk   = (const float*)d_in[2];
    const float* Wv    = (const float*)d_in[3];
    const float* bv    = (const float*)d_in[4];
    const float* Wt    = (const float*)d_in[5];
    const float* bt    = (const float*)d_in[6];
    const float* gamma = (const float*)d_in[7];
    const float* beta  = (const float*)d_in[8];
    const float* Wp    = (const float*)d_in[9];
    const float* bp    = (const float*)d_in[10];
    const float* temp  = (const float*)d_in[11];
    float* out = (float*)d_out;

    float *xT, *Yqkt, *Yv, *energy, *rmx, *rin, *colsum, *dbufT, *feat, *query;
    cudaGetSymbolAddress((void**)&xT,     g_xT);
    cudaGetSymbolAddress((void**)&Yqkt,   g_Yqkt);
    cudaGetSymbolAddress((void**)&Yv,     g_Yv);
    cudaGetSymbolAddress((void**)&energy, g_energy);
    cudaGetSymbolAddress((void**)&rmx,    g_rmax);
    cudaGetSymbolAddress((void**)&rin,    g_rinv);
    cudaGetSymbolAddress((void**)&colsum, g_colsum);
    cudaGetSymbolAddress((void**)&dbufT,  g_dbufT);
    cudaGetSymbolAddress((void**)&feat,   g_feat);
    cudaGetSymbolAddress((void**)&query,  g_query);

    const size_t CHNQ = (size_t)CH * NQ;
    const size_t NQNQ = (size_t)NQ * NQ;
    const size_t NQCH = (size_t)NQ * CH;

    cudaFuncSetAttribute(mma_gemm<3, 0, 0>, cudaFuncAttributeMaxDynamicSharedMemorySize, 65536);
    cudaFuncSetAttribute(mma_gemm<3, 1, 0>, cudaFuncAttributeMaxDynamicSharedMemorySize, 65536);
    cudaFuncSetAttribute(mma_gemm<3, 3, 0>, cudaFuncAttributeMaxDynamicSharedMemorySize, 65536);
    cudaFuncSetAttribute(mma_gemm<1, 2, 1>, cudaFuncAttributeMaxDynamicSharedMemorySize, 32768);

    dim3 blk(256);
    // xT = x^T  (b,n,c)
    transpose_x<<<dim3(NQ / 32, CH / 32, BATCH), blk>>>(x, xT);
    // Yqkt[b][n][c] = xT[n]·Wqk[c]
    mma_gemm<3, 0, 0><<<dim3(16, 2, 8), blk, 65536>>>(
        xT, NQCH, CH, Wqk, 0, CH, Yqkt, NQCH, CH, CH,
        nullptr, nullptr, nullptr, nullptr, nullptr, nullptr, nullptr);
    // Yv[b][c][n] = Wv[c]·xT[n] + bv[c]
    mma_gemm<3, 1, 0><<<dim3(2, 16, 8), blk, 65536>>>(
        Wv, 0, CH, xT, NQCH, CH, Yv, CHNQ, NQ, CH,
        bv, nullptr, nullptr, nullptr, nullptr, nullptr, nullptr);
    // energy[b][n][m] = Yqkt[n]·Yqkt[m]
    mma_gemm<3, 0, 0><<<dim3(16, 16, 8), blk, 65536>>>(
        Yqkt, NQCH, CH, Yqkt, NQCH, CH, energy, NQNQ, NQ, CH,
        nullptr, nullptr, nullptr, nullptr, nullptr, nullptr, nullptr);
    // softmax stats + column sums
    rowstat<<<BATCH * NQ, 256>>>(energy, rmx, rin);
    zero_kernel<<<(BATCH * NQ + 255) / 256, 256>>>(colsum, BATCH * NQ);
    colsum_e<<<dim3(NQ / 256, NQ / 256, BATCH), blk>>>(energy, rmx, rin, colsum);
    // dbufT[b][m][c] = x[b][c][m] - (attnT[m]·Yv[c]) / (1e-9+colsum[m]),
    // attn computed on the fly from energy
    mma_gemm<1, 2, 1><<<dim3(16, 2, 8), blk, 32768>>>(
        energy, NQNQ, NQ, Yv, CHNQ, NQ, dbufT, NQCH, CH, NQ,
        nullptr, nullptr, nullptr, x, colsum, rmx, rin);
    // feat[b][c][n] = x + relu(BN(Wt[c]·dbufT[n] + bt[c]))
    mma_gemm<3, 3, 0><<<dim3(2, 16, 8), blk, 65536>>>(
        Wt, 0, CH, dbufT, NQCH, CH, feat, CHNQ, NQ, CH,
        bt, gamma, beta, x, nullptr, nullptr, nullptr);
    // query + soft projection
    query_kernel<<<dim3(NQ / 256, BATCH), 256>>>(feat, Wp, bp, query);
    softproj_kernel<<<dim3(BATCH, NQ / 64), 256>>>(pc, query, temp, out);
}

// round 7
// speedup vs baseline: 1.2581x; 1.2581x over previous
#include <cuda_runtime.h>
#include <math.h>
#include <stdint.h>

#define BATCH 8
#define CH    256
#define NQ    2048
#define MPTS  4096
#define KNN   10

static __device__ float g_xT   [(size_t)BATCH * NQ * CH];   // (b,n,c)
static __device__ float g_Yqkt [(size_t)BATCH * NQ * CH];   // (b,n,c)
static __device__ float g_Yv   [(size_t)BATCH * CH * NQ];   // (b,c,n)
static __device__ float g_energy[(size_t)BATCH * NQ * NQ];  // (b,n,m) symmetric
static __device__ float g_rmax [BATCH * NQ];
static __device__ float g_rinv [BATCH * NQ];
static __device__ float g_colsum[BATCH * NQ];
static __device__ float g_dbufT[(size_t)BATCH * NQ * CH];   // (b,n,c)
static __device__ float g_feat [(size_t)BATCH * CH * NQ];   // (b,c,n)
static __device__ float g_query[(size_t)BATCH * 3 * NQ];

__device__ __forceinline__ uint32_t smem_u32(const void* p) {
    uint32_t a;
    asm("{ .reg .u64 t; cvta.to.shared.u64 t, %1; cvt.u32.u64 %0, t; }" : "=r"(a) : "l"(p));
    return a;
}
__device__ __forceinline__ uint32_t f2tf32(float f) {
    uint32_t r;
    asm("cvt.rna.tf32.f32 %0, %1;" : "=r"(r) : "f"(f));
    return r;
}
#define LDSM_X4(r0, r1, r2, r3, addr) \
    asm volatile("ldmatrix.sync.aligned.m8n8.x4.shared.b16 {%0,%1,%2,%3}, [%4];" \
        : "=r"(r0), "=r"(r1), "=r"(r2), "=r"(r3) : "r"(addr))
#define MMA4(d, a, bb) \
    asm volatile("mma.sync.aligned.m16n8k8.row.col.f32.tf32.tf32.f32 " \
        "{%0,%1,%2,%3}, {%4,%5,%6,%7}, {%8,%9}, {%0,%1,%2,%3};" \
        : "+f"((d)[0]), "+f"((d)[1]), "+f"((d)[2]), "+f"((d)[3]) \
        : "r"((a)[0]), "r"((a)[1]), "r"((a)[2]), "r"((a)[3]), \
          "r"((bb)[0]), "r"((bb)[1]))

// ===========================================================================
// mma.sync tf32 GEMM: D[128 x BN] = A(128 rows,K) @ B(BN rows,K)^T, K-major.
// PASSES 3: hi/lo 3xTF32 (~fp32); PASSES 1: plain tf32.
// AFILL 1: A[m][k=n] = tf32(exp(energy[n][m]-rmax[n])*rinv[n]) on the fly.
// MODE 0: Out = acc (SYMM: also write transposed tile via smem staging)
// MODE 1: Out = acc + bias[row]
// MODE 2: Out[row*ldc+col] = xT[b][row][col] - acc/(1e-9+colsum[b][row])
// MODE 3: Out = xres[b][row][col] + relu(BN(acc+bias[row]))
// Double-buffered SMEM, 1 barrier per k-chunk.
// ===========================================================================
template<int PASSES, int MODE, int AFILL, int BN, bool SYMM>
__global__ __launch_bounds__(256)
void mma_gemm(const float* __restrict__ Aall, size_t sA, int lda,
              const float* __restrict__ Ball, size_t sB, int ldb,
              float* __restrict__ Out, size_t sC, int ldc, int KTOT,
              const float* __restrict__ bias, const float* __restrict__ gamma,
              const float* __restrict__ beta, const float* __restrict__ xres,
              const float* __restrict__ colsum,
              const float* __restrict__ rmax, const float* __restrict__ rinv)
{
    extern __shared__ char DSM[];
    constexpr int NT = BN / 32;                     // n-tiles (of 8) per warp
    constexpr int AOFF_L = 16384;
    constexpr int BOFF = (PASSES == 3) ? 32768 : 16384;
    constexpr int BOFF_L = BOFF + BN * 128;
    constexpr int STAGE = (PASSES == 3) ? (32768 + BN * 256) : (16384 + BN * 128);

    const int b = blockIdx.z;
    int bi, bj;
    if (SYMM) {
        int t = blockIdx.x;
        bi = 0;
        while (t >= 16 - bi) { t -= 16 - bi; bi++; }
        bj = bi + t;
    } else { bi = blockIdx.x; bj = blockIdx.y; }
    const int a0 = bi * 128;
    const int boff = bj * BN;

    const float* Ab = Aall + (size_t)b * sA;
    const float* Arow = Ab + (size_t)a0 * lda;
    const float* Brow = Ball + (size_t)b * sB + (size_t)boff * ldb;
    const int tid = threadIdx.x, lane = tid & 31;
    const int wm = (tid >> 5) >> 2, wn = (tid >> 5) & 3;
    const uint32_t sbase = smem_u32(DSM);

    float acc[4][NT][4];
#pragma unroll
    for (int i = 0; i < 4; i++)
#pragma unroll
        for (int j = 0; j < NT; j++)
#pragma unroll
            for (int k = 0; k < 4; k++) acc[i][j][k] = 0.f;

    float4 pa[4], pb[4];
    if (AFILL == 0) {
#pragma unroll
        for (int i = 0; i < 4; i++) {
            int idx = tid + i * 256;
            pa[i] = *(const float4*)(Arow + (size_t)(idx >> 3) * lda + (idx & 7) * 4);
            pb[i] = *(const float4*)(Brow + (size_t)(idx >> 3) * ldb + (idx & 7) * 4);
        }
    }

    const int NIT = KTOT / 32;
    for (int it = 0; it < NIT; it++) {
        const int k0 = it * 32;
        char* st = DSM + (it & 1) * STAGE;
        if (AFILL == 0) {
#pragma unroll
            for (int i = 0; i < 4; i++) {
                int idx = tid + i * 256;
                int m = idx >> 3, j = idx & 7;
                uint32_t off = (uint32_t)(m * 128 + ((j * 16) ^ ((m & 7) * 16)));
                float4 v = pa[i];
                uint4 h;
                h.x = f2tf32(v.x); h.y = f2tf32(v.y); h.z = f2tf32(v.z); h.w = f2tf32(v.w);
                *(uint4*)(st + off) = h;
                if (PASSES == 3) {
                    float4 l = make_float4(v.x - __uint_as_float(h.x), v.y - __uint_as_float(h.y),
                                           v.z - __uint_as_float(h.z), v.w - __uint_as_float(h.w));
                    *(float4*)(st + AOFF_L + off) = l;
                }
                v = pb[i];
                h.x = f2tf32(v.x); h.y = f2tf32(v.y); h.z = f2tf32(v.z); h.w = f2tf32(v.w);
                *(uint4*)(st + BOFF + off) = h;
                if (PASSES == 3) {
                    float4 l = make_float4(v.x - __uint_as_float(h.x), v.y - __uint_as_float(h.y),
                                           v.z - __uint_as_float(h.z), v.w - __uint_as_float(h.w));
                    *(float4*)(st + BOFF_L + off) = l;
                }
            }
        } else {
            // A = softmax(energy)^T tile: thread owns (row m, 4 consecutive n)
#pragma unroll
            for (int i = 0; i < 4; i++) {
                int idx = tid + i * 256;
                int m = idx & 127, ng = idx >> 7;
                const float* ep = Ab + (size_t)(k0 + ng * 4) * lda + a0 + m;
                float vs[4];
#pragma unroll
                for (int j = 0; j < 4; j++) {
                    int nidx = b * NQ + k0 + ng * 4 + j;
                    vs[j] = __expf(ep[(size_t)j * lda] - rmax[nidx]) * rinv[nidx];
                }
                uint4 h;
                h.x = f2tf32(vs[0]); h.y = f2tf32(vs[1]);
                h.z = f2tf32(vs[2]); h.w = f2tf32(vs[3]);
                uint32_t off = (uint32_t)(m * 128 + ((ng * 16) ^ ((m & 7) * 16)));
                *(uint4*)(st + off) = h;
            }
            // B = Yv tile (BN x 32)
#pragma unroll
            for (int i = 0; i < BN / 32; i++) {
                int idx = tid + i * 256;
                int r = idx >> 3, j = idx & 7;
                float4 v = *(const float4*)(Brow + (size_t)r * ldb + k0 + j * 4);
                uint4 h;
                h.x = f2tf32(v.x); h.y = f2tf32(v.y); h.z = f2tf32(v.z); h.w = f2tf32(v.w);
                uint32_t off = (uint32_t)(r * 128 + ((j * 16) ^ ((r & 7) * 16)));
                *(uint4*)(st + BOFF + off) = h;
            }
        }
        __syncthreads();
        if (AFILL == 0 && it + 1 < NIT) {
            int kn = (it + 1) * 32;
#pragma unroll
            for (int i = 0; i < 4; i++) {
                int idx = tid + i * 256;
                pa[i] = *(const float4*)(Arow + (size_t)(idx >> 3) * lda + kn + (idx & 7) * 4);
                pb[i] = *(const float4*)(Brow + (size_t)(idx >> 3) * ldb + kn + (idx & 7) * 4);
            }
        }
        const uint32_t Ah = sbase + (it & 1) * STAGE, Bh = Ah + BOFF;
        const uint32_t Al = Ah + AOFF_L, Bl = Ah + BOFF_L;
#pragma unroll
        for (int ks = 0; ks < 4; ks++) {
            uint32_t ahf[4][4], bhf[NT][2], alf[4][4], blf[NT][2];
            const uint32_t ca = (uint32_t)(ks * 32 + (lane & 16));
            const int ra = wm * 64 + (lane & 15);
#pragma unroll
            for (int mt = 0; mt < 4; mt++) {
                int r = ra + mt * 16;
                uint32_t o = (uint32_t)(r * 128) + (ca ^ (uint32_t)((r & 7) * 16));
                LDSM_X4(ahf[mt][0], ahf[mt][1], ahf[mt][2], ahf[mt][3], Ah + o);
                if (PASSES == 3)
                    LDSM_X4(alf[mt][0], alf[mt][1], alf[mt][2], alf[mt][3], Al + o);
            }
            const uint32_t cb = (uint32_t)(ks * 32 + ((lane & 8) << 1));
            const int rbb = wn * (BN / 4) + (lane & 7) + ((lane & 16) >> 1);
#pragma unroll
            for (int np = 0; np < NT / 2; np++) {
                int r = rbb + np * 16;
                uint32_t o = (uint32_t)(r * 128) + (cb ^ (uint32_t)((r & 7) * 16));
                LDSM_X4(bhf[2 * np][0], bhf[2 * np][1], bhf[2 * np + 1][0], bhf[2 * np + 1][1], Bh + o);
                if (PASSES == 3)
                    LDSM_X4(blf[2 * np][0], blf[2 * np][1], blf[2 * np + 1][0], blf[2 * np + 1][1], Bl + o);
            }
#pragma unroll
            for (int mt = 0; mt < 4; mt++)
#pragma unroll
                for (int nt = 0; nt < NT; nt++) {
                    MMA4(acc[mt][nt], ahf[mt], bhf[nt]);
                    if (PASSES == 3) {
                        MMA4(acc[mt][nt], ahf[mt], blf[nt]);
                        MMA4(acc[mt][nt], alf[mt], bhf[nt]);
                    }
                }
        }
        // no trailing barrier: next fill targets the other stage
    }

    const int gid = lane >> 2, tig = lane & 3;
    float* Ob = Out + (size_t)b * sC;
    const float bns = 0.9999950000374996f;  // 1/sqrt(1+1e-5)
#pragma unroll
    for (int mt = 0; mt < 4; mt++) {
        int r0 = a0 + wm * 64 + mt * 16 + gid;
        int r1 = r0 + 8;
        if (MODE == 0 || MODE == 1) {
            float b0 = 0.f, b1 = 0.f;
            if (MODE == 1) { b0 = bias[r0]; b1 = bias[r1]; }
#pragma unroll
            for (int nt = 0; nt < NT; nt++) {
                int c = boff + wn * (BN / 4) + nt * 8 + 2 * tig;
                *(float2*)(Ob + (size_t)r0 * ldc + c) =
                    make_float2(acc[mt][nt][0] + b0, acc[mt][nt][1] + b0);
                *(float2*)(Ob + (size_t)r1 * ldc + c) =
                    make_float2(acc[mt][nt][2] + b1, acc[mt][nt][3] + b1);
            }
        } else if (MODE == 2) {
            const float* xr0 = xres + ((size_t)b * NQ + r0) * CH;
            const float* xr1 = xres + ((size_t)b * NQ + r1) * CH;
            float inv0 = 1.f / (1e-9f + colsum[b * NQ + r0]);
            float inv1 = 1.f / (1e-9f + colsum[b * NQ + r1]);
            float* o0 = Ob + (size_t)r0 * ldc;
            float* o1 = Ob + (size_t)r1 * ldc;
#pragma unroll
            for (int nt = 0; nt < NT; nt++) {
                int c = boff + wn * (BN / 4) + nt * 8 + 2 * tig;
                float2 x0 = *(const float2*)(xr0 + c);
                float2 x1 = *(const float2*)(xr1 + c);
                *(float2*)(o0 + c) = make_float2(x0.x - acc[mt][nt][0] * inv0,
                                                 x0.y - acc[mt][nt][1] * inv0);
                *(float2*)(o1 + c) = make_float2(x1.x - acc[mt][nt][2] * inv1,
                                                 x1.y - acc[mt][nt][3] * inv1);
            }
        } else {   // MODE 3
            float bb0 = bias[r0], g0 = gamma[r0], be0 = beta[r0];
            float bb1 = bias[r1], g1 = gamma[r1], be1 = beta[r1];
            const float* xb = xres + (size_t)b * CH * NQ;
#pragma unroll
            for (int nt = 0; nt < NT; nt++) {
                int c = boff + wn * (BN / 4) + nt * 8 + 2 * tig;
                float2 x0 = *(const float2*)(xb + (size_t)r0 * NQ + c);
                float2 x1 = *(const float2*)(xb + (size_t)r1 * NQ + c);
                float v0 = (acc[mt][nt][0] + bb0) * bns * g0 + be0;
                float v1 = (acc[mt][nt][1] + bb0) * bns * g0 + be0;
                float v2 = (acc[mt][nt][2] + bb1) * bns * g1 + be1;
                float v3 = (acc[mt][nt][3] + bb1) * bns * g1 + be1;
                *(float2*)(Ob + (size_t)r0 * ldc + c) =
                    make_float2(x0.x + fmaxf(v0, 0.f), x0.y + fmaxf(v1, 0.f));
                *(float2*)(Ob + (size_t)r1 * ldc + c) =
                    make_float2(x1.x + fmaxf(v2, 0.f), x1.y + fmaxf(v3, 0.f));
            }
        }
    }

    if (SYMM) {
        if (bi == bj) return;
        // mirror tile: stage acc into smem [r][c] (stride 129), write transposed
        __syncthreads();
        float* sm = (float*)DSM;
#pragma unroll
        for (int mt = 0; mt < 4; mt++) {
            int rl0 = wm * 64 + mt * 16 + gid;
#pragma unroll
            for (int nt = 0; nt < NT; nt++) {
                int cl = wn * (BN / 4) + nt * 8 + 2 * tig;
                sm[rl0 * 129 + cl]           = acc[mt][nt][0];
                sm[rl0 * 129 + cl + 1]       = acc[mt][nt][1];
                sm[(rl0 + 8) * 129 + cl]     = acc[mt][nt][2];
                sm[(rl0 + 8) * 129 + cl + 1] = acc[mt][nt][3];
            }
        }
        __syncthreads();
#pragma unroll 4
        for (int i = 0; i < 64; i++) {
            int idx = tid + i * 256;
            int rw = idx >> 7, cl = idx & 127;
            Ob[(size_t)(boff + rw) * ldc + a0 + cl] = sm[cl * 129 + rw];
        }
    }
}

// xT[b][n][c] = x[b][c][n]
__global__ __launch_bounds__(256)
void transpose_x(const float* __restrict__ x, float* __restrict__ xT)
{
    __shared__ float tl[32][33];
    const int b = blockIdx.z;
    const int n0 = blockIdx.x * 32, c0 = blockIdx.y * 32;
    const int tx = threadIdx.x & 31, ty = threadIdx.x >> 5;
#pragma unroll
    for (int i = 0; i < 4; i++)
        tl[ty + i * 8][tx] = x[(size_t)b * CH * NQ + (size_t)(c0 + ty + i * 8) * NQ + n0 + tx];
    __syncthreads();
#pragma unroll
    for (int i = 0; i < 4; i++)
        xT[(size_t)b * NQ * CH + (size_t)(n0 + ty + i * 8) * CH + c0 + tx] = tl[tx][ty + i * 8];
}

// row max + 1/sum(exp) per energy row
__global__ __launch_bounds__(256)
void rowstat(const float* __restrict__ e, float* __restrict__ rmax, float* __restrict__ rinv)
{
    const float* row = e + (size_t)blockIdx.x * NQ;
    const int t = threadIdx.x;
    float v[8], mx = -1e30f;
#pragma unroll
    for (int i = 0; i < 8; i++) { v[i] = row[t + i * 256]; mx = fmaxf(mx, v[i]); }
    __shared__ float red[8], red2[8];
#pragma unroll
    for (int off = 16; off; off >>= 1) mx = fmaxf(mx, __shfl_xor_sync(~0u, mx, off));
    if ((t & 31) == 0) red[t >> 5] = mx;
    __syncthreads();
    mx = red[0];
#pragma unroll
    for (int i = 1; i < 8; i++) mx = fmaxf(mx, red[i]);
    float s = 0.f;
#pragma unroll
    for (int i = 0; i < 8; i++) s += __expf(v[i] - mx);
#pragma unroll
    for (int off = 16; off; off >>= 1) s += __shfl_xor_sync(~0u, s, off);
    if ((t & 31) == 0) red2[t >> 5] = s;
    __syncthreads();
    if (t == 0) {
        s = red2[0];
#pragma unroll
        for (int i = 1; i < 8; i++) s += red2[i];
        rmax[blockIdx.x] = mx;
        rinv[blockIdx.x] = 1.f / s;
    }
}

__global__ void zero_kernel(float* __restrict__ p, int n)
{
    int i = blockIdx.x * blockDim.x + threadIdx.x;
    if (i < n) p[i] = 0.f;
}

// colsum[b][m] += sum_n exp(e[b][n][m]-rmax[n])*rinv[n]
__global__ __launch_bounds__(256)
void colsum_e(const float* __restrict__ e, const float* __restrict__ rmax,
              const float* __restrict__ rinv, float* __restrict__ cs)
{
    const int b = blockIdx.z;
    const int m = blockIdx.x * 256 + threadIdx.x;
    const int n0 = blockIdx.y * 256;
    const float* p = e + ((size_t)(b * NQ + n0)) * NQ + m;
    float s = 0.f;
#pragma unroll 4
    for (int n = 0; n < 256; n++) {
        int r = b * NQ + n0 + n;
        s += __expf(p[(size_t)n * NQ] - rmax[r]) * rinv[r];
    }
    atomicAdd(&cs[b * NQ + m], s);
}

// query[b][j][n] = sum_c Wp[j][c]*feat[b][c][n] + bp[j]
__global__ __launch_bounds__(256)
void query_kernel(const float* __restrict__ feat, const float* __restrict__ Wp,
                  const float* __restrict__ bp, float* __restrict__ q)
{
    const int n = blockIdx.x * 256 + threadIdx.x;
    const int b = blockIdx.y;
    const float* f = feat + (size_t)b * CH * NQ + n;
    float a0 = 0.f, a1 = 0.f, a2 = 0.f;
#pragma unroll 4
    for (int c = 0; c < CH; c++) {
        float fv = f[(size_t)c * NQ];
        a0 = fmaf(Wp[c], fv, a0);
        a1 = fmaf(Wp[CH + c], fv, a1);
        a2 = fmaf(Wp[2 * CH + c], fv, a2);
    }
    size_t o = (size_t)b * 3 * NQ + n;
    q[o] = a0 + bp[0]; q[o + NQ] = a1 + bp[1]; q[o + 2 * NQ] = a2 + bp[2];
}

// soft projection: warp-per-query top-10 + softmax weighted sum
__global__ __launch_bounds__(256)
void softproj_kernel(const float* __restrict__ pc, const float* __restrict__ query,
                     const float* __restrict__ temp, float* __restrict__ out)
{
    __shared__ float spx[MPTS], spy[MPTS], spz[MPTS];
    const int b = blockIdx.x;
    const float* p = pc + (size_t)b * 3 * MPTS;
    for (int i = threadIdx.x; i < MPTS; i += 256) {
        spx[i] = p[i]; spy[i] = p[MPTS + i]; spz[i] = p[2 * MPTS + i];
    }
    __syncthreads();

    const float t = temp[0];
    const float invsig = 1.f / (fmaxf(t * t, 1e-4f) + 1e-8f);
    const int warp = threadIdx.x >> 5, lane = threadIdx.x & 31;
    const int qbase = blockIdx.y * 64;

    for (int qq = 0; qq < 8; ++qq) {
        const int n = qbase + warp * 8 + qq;
        const float qx = query[((size_t)b * 3) * NQ + n];
        const float qy = query[((size_t)b * 3 + 1) * NQ + n];
        const float qz = query[((size_t)b * 3 + 2) * NQ + n];

        float d[KNN]; int idx[KNN];
#pragma unroll
        for (int i = 0; i < KNN; i++) { d[i] = 1e30f; idx[i] = 0; }
        for (int m = lane; m < MPTS; m += 32) {
            float dx = spx[m] - qx, dy = spy[m] - qy, dz = spz[m] - qz;
            float dd = fmaf(dx, dx, fmaf(dy, dy, dz * dz));
            if (dd < d[KNN - 1]) {
                d[KNN - 1] = dd; idx[KNN - 1] = m;
#pragma unroll
                for (int j = KNN - 1; j > 0; --j)
                    if (d[j] < d[j - 1]) {
                        float td = d[j]; d[j] = d[j - 1]; d[j - 1] = td;
                        int ti = idx[j]; idx[j] = idx[j - 1]; idx[j - 1] = ti;
                    }
            }
        }
        float wsum = 0.f, ox = 0.f, oy = 0.f, oz = 0.f, dmin = 0.f;
#pragma unroll
        for (int k = 0; k < KNN; k++) {
            float cd = d[0]; int ci = idx[0];
#pragma unroll
            for (int off = 16; off; off >>= 1) {
                float od = __shfl_xor_sync(~0u, cd, off);
                int   oi = __shfl_xor_sync(~0u, ci, off);
                if (od < cd || (od == cd && oi < ci)) { cd = od; ci = oi; }
            }
            if (k == 0) dmin = cd;
            float w = __expf(-(cd - dmin) * invsig);
            wsum += w;
            ox = fmaf(w, spx[ci], ox); oy = fmaf(w, spy[ci], oy); oz = fmaf(w, spz[ci], oz);
            bool iwin = (d[0] == cd && idx[0] == ci);
            unsigned bal = __ballot_sync(~0u, iwin);
            if (lane == (__ffs(bal) - 1)) {
#pragma unroll
                for (int j = 0; j < KNN - 1; j++) { d[j] = d[j + 1]; idx[j] = idx[j + 1]; }
                d[KNN - 1] = 1e30f; idx[KNN - 1] = 0;
            }
        }
        if (lane == 0) {
            float inv = 1.f / wsum;
            out[((size_t)b * 3) * NQ + n] = ox * inv;
            out[((size_t)b * 3 + 1) * NQ + n] = oy * inv;
            out[((size_t)b * 3 + 2) * NQ + n] = oz * inv;
        }
    }
}

// ---------------------------------------------------------------------------
extern "C" void kernel_launch(void* const* d_in, const int* in_sizes, int n_in,
                              void* d_out, int out_size)
{
    const float* x     = (const float*)d_in[0];
    const float* pc    = (const float*)d_in[1];
    const float* Wqk   = (const float*)d_in[2];
    const float* Wv    = (const float*)d_in[3];
    const float* bv    = (const float*)d_in[4];
    const float* Wt    = (const float*)d_in[5];
    const float* bt    = (const float*)d_in[6];
    const float* gamma = (const float*)d_in[7];
    const float* beta  = (const float*)d_in[8];
    const float* Wp    = (const float*)d_in[9];
    const float* bp    = (const float*)d_in[10];
    const float* temp  = (const float*)d_in[11];
    float* out = (float*)d_out;

    float *xT, *Yqkt, *Yv, *energy, *rmx, *rin, *colsum, *dbufT, *feat, *query;
    cudaGetSymbolAddress((void**)&xT,     g_xT);
    cudaGetSymbolAddress((void**)&Yqkt,   g_Yqkt);
    cudaGetSymbolAddress((void**)&Yv,     g_Yv);
    cudaGetSymbolAddress((void**)&energy, g_energy);
    cudaGetSymbolAddress((void**)&rmx,    g_rmax);
    cudaGetSymbolAddress((void**)&rin,    g_rinv);
    cudaGetSymbolAddress((void**)&colsum, g_colsum);
    cudaGetSymbolAddress((void**)&dbufT,  g_dbufT);
    cudaGetSymbolAddress((void**)&feat,   g_feat);
    cudaGetSymbolAddress((void**)&query,  g_query);

    const size_t CHNQ = (size_t)CH * NQ;
    const size_t NQNQ = (size_t)NQ * NQ;
    const size_t NQCH = (size_t)NQ * CH;

    // smem: 3x BN128 stage=64KB -> 128KB; 1x BN256 stage=48KB -> 96KB
    cudaFuncSetAttribute(mma_gemm<3, 0, 0, 128, false>, cudaFuncAttributeMaxDynamicSharedMemorySize, 131072);
    cudaFuncSetAttribute(mma_gemm<3, 1, 0, 128, false>, cudaFuncAttributeMaxDynamicSharedMemorySize, 131072);
    cudaFuncSetAttribute(mma_gemm<3, 0, 0, 128, true >, cudaFuncAttributeMaxDynamicSharedMemorySize, 131072);
    cudaFuncSetAttribute(mma_gemm<3, 3, 0, 128, false>, cudaFuncAttributeMaxDynamicSharedMemorySize, 131072);
    cudaFuncSetAttribute(mma_gemm<1, 2, 1, 256, false>, cudaFuncAttributeMaxDynamicSharedMemorySize, 98304);

    dim3 blk(256);
    // xT = x^T  (b,n,c)
    transpose_x<<<dim3(NQ / 32, CH / 32, BATCH), blk>>>(x, xT);
    // Yqkt[b][n][c] = xT[n]·Wqk[c]
    mma_gemm<3, 0, 0, 128, false><<<dim3(16, 2, 8), blk, 131072>>>(
        xT, NQCH, CH, Wqk, 0, CH, Yqkt, NQCH, CH, CH,
        nullptr, nullptr, nullptr, nullptr, nullptr, nullptr, nullptr);
    // Yv[b][c][n] = Wv[c]·xT[n] + bv[c]
    mma_gemm<3, 1, 0, 128, false><<<dim3(2, 16, 8), blk, 131072>>>(
        Wv, 0, CH, xT, NQCH, CH, Yv, CHNQ, NQ, CH,
        bv, nullptr, nullptr, nullptr, nullptr, nullptr, nullptr);
    // energy[b][n][m] = Yqkt[n]·Yqkt[m]  (symmetric: upper-triangle tiles only)
    mma_gemm<3, 0, 0, 128, true><<<dim3(136, 1, 8), blk, 131072>>>(
        Yqkt, NQCH, CH, Yqkt, NQCH, CH, energy, NQNQ, NQ, CH,
        nullptr, nullptr, nullptr, nullptr, nullptr, nullptr, nullptr);
    // softmax stats + column sums
    rowstat<<<BATCH * NQ, 256>>>(energy, rmx, rin);
    zero_kernel<<<(BATCH * NQ + 255) / 256, 256>>>(colsum, BATCH * NQ);
    colsum_e<<<dim3(NQ / 256, NQ / 256, BATCH), blk>>>(energy, rmx, rin, colsum);
    // dbufT[b][m][c] = xT[b][m][c] - (attnT[m]·Yv[c]) / (1e-9+colsum[m])
    mma_gemm<1, 2, 1, 256, false><<<dim3(16, 1, 8), blk, 98304>>>(
        energy, NQNQ, NQ, Yv, CHNQ, NQ, dbufT, NQCH, CH, NQ,
        nullptr, nullptr, nullptr, xT, colsum, rmx, rin);
    // feat[b][c][n] = x + relu(BN(Wt[c]·dbufT[n] + bt[c]))
    mma_gemm<3, 3, 0, 128, false><<<dim3(2, 16, 8), blk, 131072>>>(
        Wt, 0, CH, dbufT, NQCH, CH, feat, CHNQ, NQ, CH,
        bt, gamma, beta, x, nullptr, nullptr, nullptr);
    // query + soft projection
    query_kernel<<<dim3(NQ / 256, BATCH), 256>>>(feat, Wp, bp, query);
    softproj_kernel<<<dim3(BATCH, NQ / 64), 256>>>(pc, query, temp, out);
}

// round 8
// speedup vs baseline: 1.2670x; 1.0070x over previous
#include <cuda_runtime.h>
#include <math.h>
#include <stdint.h>

#define BATCH 8
#define CH    256
#define NQ    2048
#define MPTS  4096
#define KNN   10

static __device__ float g_xT   [(size_t)BATCH * NQ * CH];   // (b,n,c)
static __device__ float g_Yqkt [(size_t)BATCH * NQ * CH];   // (b,n,c)
static __device__ float g_Yv   [(size_t)BATCH * CH * NQ];   // (b,c,n)
static __device__ float g_energy[(size_t)BATCH * NQ * NQ];  // (b,n,m) symmetric
static __device__ float g_rmax [BATCH * NQ];
static __device__ float g_rinv [BATCH * NQ];
static __device__ float g_dbufT[(size_t)BATCH * NQ * CH];   // (b,n,c)
static __device__ float g_feat [(size_t)BATCH * CH * NQ];   // (b,c,n)
static __device__ float g_query[(size_t)BATCH * 3 * NQ];

__device__ __forceinline__ uint32_t smem_u32(const void* p) {
    uint32_t a;
    asm("{ .reg .u64 t; cvta.to.shared.u64 t, %1; cvt.u32.u64 %0, t; }" : "=r"(a) : "l"(p));
    return a;
}
__device__ __forceinline__ uint32_t f2tf32(float f) {
    uint32_t r;
    asm("cvt.rna.tf32.f32 %0, %1;" : "=r"(r) : "f"(f));
    return r;
}
__device__ __forceinline__ void tf32split(uint32_t raw, uint32_t& h, uint32_t& l) {
    float f = __uint_as_float(raw);
    uint32_t hh;
    asm("cvt.rna.tf32.f32 %0, %1;" : "=r"(hh) : "f"(f));
    h = hh;
    l = __float_as_uint(f - __uint_as_float(hh));
}
__device__ __forceinline__ void cp16(uint32_t dst, const float* src) {
    asm volatile("cp.async.ca.shared.global [%0], [%1], 16;" :: "r"(dst), "l"(src) : "memory");
}
#define CP_COMMIT() asm volatile("cp.async.commit_group;" ::: "memory")
#define CP_WAIT1()  asm volatile("cp.async.wait_group 1;" ::: "memory")
#define CP_WAIT0()  asm volatile("cp.async.wait_group 0;" ::: "memory")
#define LDSM_X4(r0, r1, r2, r3, addr) \
    asm volatile("ldmatrix.sync.aligned.m8n8.x4.shared.b16 {%0,%1,%2,%3}, [%4];" \
        : "=r"(r0), "=r"(r1), "=r"(r2), "=r"(r3) : "r"(addr))
#define MMA4(d, a, bb) \
    asm volatile("mma.sync.aligned.m16n8k8.row.col.f32.tf32.tf32.f32 " \
        "{%0,%1,%2,%3}, {%4,%5,%6,%7}, {%8,%9}, {%0,%1,%2,%3};" \
        : "+f"((d)[0]), "+f"((d)[1]), "+f"((d)[2]), "+f"((d)[3]) \
        : "r"((a)[0]), "r"((a)[1]), "r"((a)[2]), "r"((a)[3]), \
          "r"((bb)[0]), "r"((bb)[1]))

// ===========================================================================
// mma.sync tf32 GEMM: D[128 x BN] = A(128 rows,K) @ B(BN rows,K)^T, K-major.
// Raw fp32 tiles in SMEM (hi/lo split in registers post-ldmatrix).
// 3-stage cp.async pipeline. PASSES 3: 3xTF32; PASSES 1: plain tf32.
// AFILL 1: A[m][k=n] = exp(energy[n][m]-rmax[n])*rinv[n], computed 2 ahead;
//          also accumulates colsum (fused).
// MODE 0: Out = acc (SYMM: + mirrored transpose tile)
// MODE 1: Out = acc + bias[row]
// MODE 2: Out[row*ldc+col] = xT[b][row][col] - acc/(1e-9+colsum_smem[row])
// MODE 3: Out = xres[b][row][col] + relu(BN(acc+bias[row]))
// ===========================================================================
template<int PASSES, int MODE, int AFILL, int BN, bool SYMM>
__global__ __launch_bounds__(256)
void mma_gemm(const float* __restrict__ Aall, size_t sA, int lda,
              const float* __restrict__ Ball, size_t sB, int ldb,
              float* __restrict__ Out, size_t sC, int ldc, int KTOT,
              const float* __restrict__ bias, const float* __restrict__ gamma,
              const float* __restrict__ beta, const float* __restrict__ xres,
              const float* __restrict__ rmax, const float* __restrict__ rinv)
{
    extern __shared__ char DSM[];
    constexpr int NT = BN / 32;
    constexpr int ABYTES = 16384;
    constexpr int STAGE = ABYTES + BN * 128;

    const int b = blockIdx.z;
    int bi, bj;
    if (SYMM) {
        int t = blockIdx.x;
        bi = 0;
        while (t >= 16 - bi) { t -= 16 - bi; bi++; }
        bj = bi + t;
    } else { bi = blockIdx.x; bj = blockIdx.y; }
    const int a0 = bi * 128;
    const int boff = bj * BN;

    const float* Ab = Aall + (size_t)b * sA;
    const float* Arow = Ab + (size_t)a0 * lda;
    const float* Brow = Ball + (size_t)b * sB + (size_t)boff * ldb;
    const int tid = threadIdx.x, lane = tid & 31;
    const int wm = (tid >> 5) >> 2, wn = (tid >> 5) & 3;
    const uint32_t sbase = smem_u32(DSM);

    float acc[4][NT][4];
#pragma unroll
    for (int i = 0; i < 4; i++)
#pragma unroll
        for (int j = 0; j < NT; j++)
#pragma unroll
            for (int k = 0; k < 4; k++) acc[i][j][k] = 0.f;

    float csum = 0.f;
    const int NIT = KTOT / 32;

    auto fill = [&](int it) {
        const int k0 = it * 32;
        const uint32_t st = sbase + (it % 3) * STAGE;
        char* stc = DSM + (it % 3) * STAGE;
        if (AFILL == 0) {
#pragma unroll
            for (int i = 0; i < 4; i++) {
                int idx = tid + i * 256;
                int m = idx >> 3, j = idx & 7;
                uint32_t off = (uint32_t)(m * 128 + ((j * 16) ^ ((m & 7) * 16)));
                cp16(st + off, Arow + (size_t)m * lda + k0 + j * 4);
            }
        } else {
#pragma unroll
            for (int i = 0; i < 4; i++) {
                int idx = tid + i * 256;
                int m = idx & 127, ng = idx >> 7;
                const float* ep = Ab + (size_t)(k0 + ng * 4) * lda + a0 + m;
                int nb = b * NQ + k0 + ng * 4;
                float4 vs;
                vs.x = __expf(ep[0]              - rmax[nb + 0]) * rinv[nb + 0];
                vs.y = __expf(ep[(size_t)lda]    - rmax[nb + 1]) * rinv[nb + 1];
                vs.z = __expf(ep[(size_t)2*lda]  - rmax[nb + 2]) * rinv[nb + 2];
                vs.w = __expf(ep[(size_t)3*lda]  - rmax[nb + 3]) * rinv[nb + 3];
                csum += vs.x + vs.y + vs.z + vs.w;
                uint32_t off = (uint32_t)(m * 128 + ((ng * 16) ^ ((m & 7) * 16)));
                *(float4*)(stc + off) = vs;
            }
        }
#pragma unroll
        for (int i = 0; i < BN / 32; i++) {
            int idx = tid + i * 256;
            int m = idx >> 3, j = idx & 7;
            uint32_t off = (uint32_t)(m * 128 + ((j * 16) ^ ((m & 7) * 16)));
            cp16(st + ABYTES + off, Brow + (size_t)m * ldb + k0 + j * 4);
        }
        CP_COMMIT();
    };

    fill(0);
    fill(1);
    for (int it = 0; it < NIT; it++) {
        CP_WAIT1();
        __syncthreads();
        if (it + 2 < NIT) fill(it + 2); else CP_COMMIT();

        const uint32_t Ah = sbase + (it % 3) * STAGE, Bh = Ah + ABYTES;
#pragma unroll
        for (int ks = 0; ks < 4; ks++) {
            uint32_t ar[4][4], ah[4][4], al[4][4];
            const uint32_t ca = (uint32_t)(ks * 32 + (lane & 16));
            const int ra = wm * 64 + (lane & 15);
#pragma unroll
            for (int mt = 0; mt < 4; mt++) {
                int r = ra + mt * 16;
                uint32_t o = (uint32_t)(r * 128) + (ca ^ (uint32_t)((r & 7) * 16));
                LDSM_X4(ar[mt][0], ar[mt][1], ar[mt][2], ar[mt][3], Ah + o);
            }
            uint32_t br[NT][2], bh[NT][2], bl[NT][2];
            const uint32_t cb = (uint32_t)(ks * 32 + ((lane & 8) << 1));
            const int rbb = wn * (BN / 4) + (lane & 7) + ((lane & 16) >> 1);
#pragma unroll
            for (int np = 0; np < NT / 2; np++) {
                int r = rbb + np * 16;
                uint32_t o = (uint32_t)(r * 128) + (cb ^ (uint32_t)((r & 7) * 16));
                LDSM_X4(br[2 * np][0], br[2 * np][1], br[2 * np + 1][0], br[2 * np + 1][1], Bh + o);
            }
            if (PASSES == 3) {
#pragma unroll
                for (int mt = 0; mt < 4; mt++)
#pragma unroll
                    for (int q = 0; q < 4; q++) tf32split(ar[mt][q], ah[mt][q], al[mt][q]);
#pragma unroll
                for (int nt = 0; nt < NT; nt++)
#pragma unroll
                    for (int q = 0; q < 2; q++) tf32split(br[nt][q], bh[nt][q], bl[nt][q]);
#pragma unroll
                for (int mt = 0; mt < 4; mt++)
#pragma unroll
                    for (int nt = 0; nt < NT; nt++) {
                        MMA4(acc[mt][nt], ah[mt], bh[nt]);
                        MMA4(acc[mt][nt], ah[mt], bl[nt]);
                        MMA4(acc[mt][nt], al[mt], bh[nt]);
                    }
            } else {
#pragma unroll
                for (int mt = 0; mt < 4; mt++)
#pragma unroll
                    for (int q = 0; q < 4; q++) ah[mt][q] = f2tf32(__uint_as_float(ar[mt][q]));
#pragma unroll
                for (int nt = 0; nt < NT; nt++)
#pragma unroll
                    for (int q = 0; q < 2; q++) bh[nt][q] = f2tf32(__uint_as_float(br[nt][q]));
#pragma unroll
                for (int mt = 0; mt < 4; mt++)
#pragma unroll
                    for (int nt = 0; nt < NT; nt++) MMA4(acc[mt][nt], ah[mt], bh[nt]);
            }
        }
        __syncthreads();
    }

    CP_WAIT0();
    __syncthreads();

    float* csA = (float*)DSM;   // reuse stages (all reads done)
    if (MODE == 2) {
        csA[tid] = csum;
        __syncthreads();
    }

    const int gid = lane >> 2, tig = lane & 3;
    float* Ob = Out + (size_t)b * sC;
    const float bns = 0.9999950000374996f;  // 1/sqrt(1+1e-5)
#pragma unroll
    for (int mt = 0; mt < 4; mt++) {
        int lm0 = wm * 64 + mt * 16 + gid;
        int r0 = a0 + lm0, r1 = r0 + 8;
        if (MODE == 0 || MODE == 1) {
            float b0 = 0.f, b1 = 0.f;
            if (MODE == 1) { b0 = bias[r0]; b1 = bias[r1]; }
#pragma unroll
            for (int nt = 0; nt < NT; nt++) {
                int c = boff + wn * (BN / 4) + nt * 8 + 2 * tig;
                *(float2*)(Ob + (size_t)r0 * ldc + c) =
                    make_float2(acc[mt][nt][0] + b0, acc[mt][nt][1] + b0);
                *(float2*)(Ob + (size_t)r1 * ldc + c) =
                    make_float2(acc[mt][nt][2] + b1, acc[mt][nt][3] + b1);
            }
        } else if (MODE == 2) {
            const float* xr0 = xres + ((size_t)b * NQ + r0) * CH;
            const float* xr1 = xres + ((size_t)b * NQ + r1) * CH;
            float inv0 = 1.f / (1e-9f + csA[lm0] + csA[lm0 + 128]);
            float inv1 = 1.f / (1e-9f + csA[lm0 + 8] + csA[lm0 + 136]);
            float* o0 = Ob + (size_t)r0 * ldc;
            float* o1 = Ob + (size_t)r1 * ldc;
#pragma unroll
            for (int nt = 0; nt < NT; nt++) {
                int c = boff + wn * (BN / 4) + nt * 8 + 2 * tig;
                float2 x0 = *(const float2*)(xr0 + c);
                float2 x1 = *(const float2*)(xr1 + c);
                *(float2*)(o0 + c) = make_float2(x0.x - acc[mt][nt][0] * inv0,
                                                 x0.y - acc[mt][nt][1] * inv0);
                *(float2*)(o1 + c) = make_float2(x1.x - acc[mt][nt][2] * inv1,
                                                 x1.y - acc[mt][nt][3] * inv1);
            }
        } else {   // MODE 3
            float bb0 = bias[r0], g0 = gamma[r0], be0 = beta[r0];
            float bb1 = bias[r1], g1 = gamma[r1], be1 = beta[r1];
            const float* xb = xres + (size_t)b * CH * NQ;
#pragma unroll
            for (int nt = 0; nt < NT; nt++) {
                int c = boff + wn * (BN / 4) + nt * 8 + 2 * tig;
                float2 x0 = *(const float2*)(xb + (size_t)r0 * NQ + c);
                float2 x1 = *(const float2*)(xb + (size_t)r1 * NQ + c);
                float v0 = (acc[mt][nt][0] + bb0) * bns * g0 + be0;
                float v1 = (acc[mt][nt][1] + bb0) * bns * g0 + be0;
                float v2 = (acc[mt][nt][2] + bb1) * bns * g1 + be1;
                float v3 = (acc[mt][nt][3] + bb1) * bns * g1 + be1;
                *(float2*)(Ob + (size_t)r0 * ldc + c) =
                    make_float2(x0.x + fmaxf(v0, 0.f), x0.y + fmaxf(v1, 0.f));
                *(float2*)(Ob + (size_t)r1 * ldc + c) =
                    make_float2(x1.x + fmaxf(v2, 0.f), x1.y + fmaxf(v3, 0.f));
            }
        }
    }

    if (SYMM) {
        if (bi == bj) return;
        __syncthreads();
        float* sm = (float*)DSM;
#pragma unroll
        for (int mt = 0; mt < 4; mt++) {
            int rl0 = wm * 64 + mt * 16 + gid;
#pragma unroll
            for (int nt = 0; nt < NT; nt++) {
                int cl = wn * (BN / 4) + nt * 8 + 2 * tig;
                sm[rl0 * 129 + cl]           = acc[mt][nt][0];
                sm[rl0 * 129 + cl + 1]       = acc[mt][nt][1];
                sm[(rl0 + 8) * 129 + cl]     = acc[mt][nt][2];
                sm[(rl0 + 8) * 129 + cl + 1] = acc[mt][nt][3];
            }
        }
        __syncthreads();
#pragma unroll 4
        for (int i = 0; i < 64; i++) {
            int idx = tid + i * 256;
            int rw = idx >> 7, cl = idx & 127;
            Ob[(size_t)(boff + rw) * ldc + a0 + cl] = sm[cl * 129 + rw];
        }
    }
}

// xT[b][n][c] = x[b][c][n]
__global__ __launch_bounds__(256)
void transpose_x(const float* __restrict__ x, float* __restrict__ xT)
{
    __shared__ float tl[32][33];
    const int b = blockIdx.z;
    const int n0 = blockIdx.x * 32, c0 = blockIdx.y * 32;
    const int tx = threadIdx.x & 31, ty = threadIdx.x >> 5;
#pragma unroll
    for (int i = 0; i < 4; i++)
        tl[ty + i * 8][tx] = x[(size_t)b * CH * NQ + (size_t)(c0 + ty + i * 8) * NQ + n0 + tx];
    __syncthreads();
#pragma unroll
    for (int i = 0; i < 4; i++)
        xT[(size_t)b * NQ * CH + (size_t)(n0 + ty + i * 8) * CH + c0 + tx] = tl[tx][ty + i * 8];
}

// row max + 1/sum(exp) per energy row
__global__ __launch_bounds__(256)
void rowstat(const float* __restrict__ e, float* __restrict__ rmax, float* __restrict__ rinv)
{
    const float* row = e + (size_t)blockIdx.x * NQ;
    const int t = threadIdx.x;
    float v[8], mx = -1e30f;
#pragma unroll
    for (int i = 0; i < 8; i++) { v[i] = row[t + i * 256]; mx = fmaxf(mx, v[i]); }
    __shared__ float red[8], red2[8];
#pragma unroll
    for (int off = 16; off; off >>= 1) mx = fmaxf(mx, __shfl_xor_sync(~0u, mx, off));
    if ((t & 31) == 0) red[t >> 5] = mx;
    __syncthreads();
    mx = red[0];
#pragma unroll
    for (int i = 1; i < 8; i++) mx = fmaxf(mx, red[i]);
    float s = 0.f;
#pragma unroll
    for (int i = 0; i < 8; i++) s += __expf(v[i] - mx);
#pragma unroll
    for (int off = 16; off; off >>= 1) s += __shfl_xor_sync(~0u, s, off);
    if ((t & 31) == 0) red2[t >> 5] = s;
    __syncthreads();
    if (t == 0) {
        s = red2[0];
#pragma unroll
        for (int i = 1; i < 8; i++) s += red2[i];
        rmax[blockIdx.x] = mx;
        rinv[blockIdx.x] = 1.f / s;
    }
}

// query[b][j][n] = sum_c Wp[j][c]*feat[b][c][n] + bp[j]
__global__ __launch_bounds__(256)
void query_kernel(const float* __restrict__ feat, const float* __restrict__ Wp,
                  const float* __restrict__ bp, float* __restrict__ q)
{
    const int n = blockIdx.x * 256 + threadIdx.x;
    const int b = blockIdx.y;
    const float* f = feat + (size_t)b * CH * NQ + n;
    float a0 = 0.f, a1 = 0.f, a2 = 0.f;
#pragma unroll 4
    for (int c = 0; c < CH; c++) {
        float fv = f[(size_t)c * NQ];
        a0 = fmaf(Wp[c], fv, a0);
        a1 = fmaf(Wp[CH + c], fv, a1);
        a2 = fmaf(Wp[2 * CH + c], fv, a2);
    }
    size_t o = (size_t)b * 3 * NQ + n;
    q[o] = a0 + bp[0]; q[o + NQ] = a1 + bp[1]; q[o + 2 * NQ] = a2 + bp[2];
}

// soft projection: warp-per-query top-10 + softmax weighted sum
__global__ __launch_bounds__(256)
void softproj_kernel(const float* __restrict__ pc, const float* __restrict__ query,
                     const float* __restrict__ temp, float* __restrict__ out)
{
    __shared__ float spx[MPTS], spy[MPTS], spz[MPTS];
    const int b = blockIdx.x;
    const float* p = pc + (size_t)b * 3 * MPTS;
    for (int i = threadIdx.x; i < MPTS; i += 256) {
        spx[i] = p[i]; spy[i] = p[MPTS + i]; spz[i] = p[2 * MPTS + i];
    }
    __syncthreads();

    const float t = temp[0];
    const float invsig = 1.f / (fmaxf(t * t, 1e-4f) + 1e-8f);
    const int warp = threadIdx.x >> 5, lane = threadIdx.x & 31;
    const int qbase = blockIdx.y * 64;

    for (int qq = 0; qq < 8; ++qq) {
        const int n = qbase + warp * 8 + qq;
        const float qx = query[((size_t)b * 3) * NQ + n];
        const float qy = query[((size_t)b * 3 + 1) * NQ + n];
        const float qz = query[((size_t)b * 3 + 2) * NQ + n];

        float d[KNN]; int idx[KNN];
#pragma unroll
        for (int i = 0; i < KNN; i++) { d[i] = 1e30f; idx[i] = 0; }
        for (int m = lane; m < MPTS; m += 32) {
            float dx = spx[m] - qx, dy = spy[m] - qy, dz = spz[m] - qz;
            float dd = fmaf(dx, dx, fmaf(dy, dy, dz * dz));
            if (dd < d[KNN - 1]) {
                d[KNN - 1] = dd; idx[KNN - 1] = m;
#pragma unroll
                for (int j = KNN - 1; j > 0; --j)
                    if (d[j] < d[j - 1]) {
                        float td = d[j]; d[j] = d[j - 1]; d[j - 1] = td;
                        int ti = idx[j]; idx[j] = idx[j - 1]; idx[j - 1] = ti;
                    }
            }
        }
        float wsum = 0.f, ox = 0.f, oy = 0.f, oz = 0.f, dmin = 0.f;
#pragma unroll
        for (int k = 0; k < KNN; k++) {
            float cd = d[0]; int ci = idx[0];
#pragma unroll
            for (int off = 16; off; off >>= 1) {
                float od = __shfl_xor_sync(~0u, cd, off);
                int   oi = __shfl_xor_sync(~0u, ci, off);
                if (od < cd || (od == cd && oi < ci)) { cd = od; ci = oi; }
            }
            if (k == 0) dmin = cd;
            float w = __expf(-(cd - dmin) * invsig);
            wsum += w;
            ox = fmaf(w, spx[ci], ox); oy = fmaf(w, spy[ci], oy); oz = fmaf(w, spz[ci], oz);
            bool iwin = (d[0] == cd && idx[0] == ci);
            unsigned bal = __ballot_sync(~0u, iwin);
            if (lane == (__ffs(bal) - 1)) {
#pragma unroll
                for (int j = 0; j < KNN - 1; j++) { d[j] = d[j + 1]; idx[j] = idx[j + 1]; }
                d[KNN - 1] = 1e30f; idx[KNN - 1] = 0;
            }
        }
        if (lane == 0) {
            float inv = 1.f / wsum;
            out[((size_t)b * 3) * NQ + n] = ox * inv;
            out[((size_t)b * 3 + 1) * NQ + n] = oy * inv;
            out[((size_t)b * 3 + 2) * NQ + n] = oz * inv;
        }
    }
}

// ---------------------------------------------------------------------------
extern "C" void kernel_launch(void* const* d_in, const int* in_sizes, int n_in,
                              void* d_out, int out_size)
{
    const float* x     = (const float*)d_in[0];
    const float* pc    = (const float*)d_in[1];
    const float* Wqk   = (const float*)d_in[2];
    const float* Wv    = (const float*)d_in[3];
    const float* bv    = (const float*)d_in[4];
    const float* Wt    = (const float*)d_in[5];
    const float* bt    = (const float*)d_in[6];
    const float* gamma = (const float*)d_in[7];
    const float* beta  = (const float*)d_in[8];
    const float* Wp    = (const float*)d_in[9];
    const float* bp    = (const float*)d_in[10];
    const float* temp  = (const float*)d_in[11];
    float* out = (float*)d_out;

    float *xT, *Yqkt, *Yv, *energy, *rmx, *rin, *dbufT, *feat, *query;
    cudaGetSymbolAddress((void**)&xT,     g_xT);
    cudaGetSymbolAddress((void**)&Yqkt,   g_Yqkt);
    cudaGetSymbolAddress((void**)&Yv,     g_Yv);
    cudaGetSymbolAddress((void**)&energy, g_energy);
    cudaGetSymbolAddress((void**)&rmx,    g_rmax);
    cudaGetSymbolAddress((void**)&rin,    g_rinv);
    cudaGetSymbolAddress((void**)&dbufT,  g_dbufT);
    cudaGetSymbolAddress((void**)&feat,   g_feat);
    cudaGetSymbolAddress((void**)&query,  g_query);

    const size_t CHNQ = (size_t)CH * NQ;
    const size_t NQNQ = (size_t)NQ * NQ;
    const size_t NQCH = (size_t)NQ * CH;

    // 3 stages: BN=128 -> 3*32KB = 96KB (>= 66KB mirror staging); BN=256 -> 144KB
    cudaFuncSetAttribute(mma_gemm<3, 0, 0, 128, false>, cudaFuncAttributeMaxDynamicSharedMemorySize, 98304);
    cudaFuncSetAttribute(mma_gemm<3, 1, 0, 128, false>, cudaFuncAttributeMaxDynamicSharedMemorySize, 98304);
    cudaFuncSetAttribute(mma_gemm<3, 0, 0, 128, true >, cudaFuncAttributeMaxDynamicSharedMemorySize, 98304);
    cudaFuncSetAttribute(mma_gemm<3, 3, 0, 128, false>, cudaFuncAttributeMaxDynamicSharedMemorySize, 98304);
    cudaFuncSetAttribute(mma_gemm<1, 2, 1, 256, false>, cudaFuncAttributeMaxDynamicSharedMemorySize, 147456);

    dim3 blk(256);
    // xT = x^T  (b,n,c)
    transpose_x<<<dim3(NQ / 32, CH / 32, BATCH), blk>>>(x, xT);
    // Yqkt[b][n][c] = xT[n]·Wqk[c]
    mma_gemm<3, 0, 0, 128, false><<<dim3(16, 2, 8), blk, 98304>>>(
        xT, NQCH, CH, Wqk, 0, CH, Yqkt, NQCH, CH, CH,
        nullptr, nullptr, nullptr, nullptr, nullptr, nullptr);
    // Yv[b][c][n] = Wv[c]·xT[n] + bv[c]
    mma_gemm<3, 1, 0, 128, false><<<dim3(2, 16, 8), blk, 98304>>>(
        Wv, 0, CH, xT, NQCH, CH, Yv, CHNQ, NQ, CH,
        bv, nullptr, nullptr, nullptr, nullptr, nullptr);
    // energy[b][n][m] = Yqkt[n]·Yqkt[m]  (symmetric, upper-triangle tiles)
    mma_gemm<3, 0, 0, 128, true><<<dim3(136, 1, 8), blk, 98304>>>(
        Yqkt, NQCH, CH, Yqkt, NQCH, CH, energy, NQNQ, NQ, CH,
        nullptr, nullptr, nullptr, nullptr, nullptr, nullptr);
    // softmax row stats
    rowstat<<<BATCH * NQ, 256>>>(energy, rmx, rin);
    // dbufT[b][m][c] = xT[b][m][c] - (attnT[m]·Yv[c]) / (1e-9+colsum[m]), colsum fused
    mma_gemm<1, 2, 1, 256, false><<<dim3(16, 1, 8), blk, 147456>>>(
        energy, NQNQ, NQ, Yv, CHNQ, NQ, dbufT, NQCH, CH, NQ,
        nullptr, nullptr, nullptr, xT, rmx, rin);
    // feat[b][c][n] = x + relu(BN(Wt[c]·dbufT[n] + bt[c]))
    mma_gemm<3, 3, 0, 128, false><<<dim3(2, 16, 8), blk, 98304>>>(
        Wt, 0, CH, dbufT, NQCH, CH, feat, CHNQ, NQ, CH,
        bt, gamma, beta, x, nullptr, nullptr);
    // query + soft projection
    query_kernel<<<dim3(NQ / 256, BATCH), 256>>>(feat, Wp, bp, query);
    softproj_kernel<<<dim3(BATCH, NQ / 64), 256>>>(pc, query, temp, out);
}